// round 14
// baseline (speedup 1.0000x reference)
#include <cuda_runtime.h>
#include <cuda_bf16.h>
#include <cstdint>
#include <math.h>

// ===========================================================================
// WindowAttentionV2: int8 two-digit qkv GEMM + split-bf16 fused attn+proj.
// B=2048 win, N=64 tok, C=256, H=8, D=32.
// ===========================================================================

// ---- device scratch --------------------------------------------------------
__device__ float g_qkv[3u * 2048 * 8 * 2048];          // [(sec*2048+win)*8+h][tok*32+d]
__device__ char  g_xq_hi[131072u * 256];               // int8 hi digit of x
__device__ char  g_xq_lo[131072u * 256];               // int8 lo digit
__device__ float g_sx[131072];                         // per-row scale of x
__device__ char  g_wq_hi[768 * 256];                   // qkv w int8 hi, [n][k]
__device__ char  g_wq_lo[768 * 256];
__device__ float g_swq[768];                           // per-col scale
__device__ __nv_bfloat16 g_wproj_hi[256 * 256];        // proj w bf16 hi/lo [n][k]
__device__ __nv_bfloat16 g_wproj_lo[256 * 256];
__device__ float g_rel_bias[8 * 64 * 64];
__device__ float g_bias_qkv[768];

// ---- helpers ----------------------------------------------------------------
__device__ __forceinline__ uint32_t smem_u32(const void* p) {
    uint32_t a;
    asm("{ .reg .u64 t; cvta.to.shared.u64 t, %1; cvt.u32.u64 %0, t; }"
        : "=r"(a) : "l"(p));
    return a;
}
__device__ __forceinline__ void mma_bf16(float* c, const uint32_t* a, const uint32_t* b) {
    asm volatile(
        "mma.sync.aligned.m16n8k16.row.col.f32.bf16.bf16.f32 "
        "{%0,%1,%2,%3}, {%4,%5,%6,%7}, {%8,%9}, {%0,%1,%2,%3};"
        : "+f"(c[0]), "+f"(c[1]), "+f"(c[2]), "+f"(c[3])
        : "r"(a[0]), "r"(a[1]), "r"(a[2]), "r"(a[3]), "r"(b[0]), "r"(b[1]));
}
__device__ __forceinline__ void mma_s8(int* c, const uint32_t* a, const uint32_t* b) {
    asm volatile(
        "mma.sync.aligned.m16n8k32.row.col.s32.s8.s8.s32 "
        "{%0,%1,%2,%3}, {%4,%5,%6,%7}, {%8,%9}, {%0,%1,%2,%3};"
        : "+r"(c[0]), "+r"(c[1]), "+r"(c[2]), "+r"(c[3])
        : "r"(a[0]), "r"(a[1]), "r"(a[2]), "r"(a[3]), "r"(b[0]), "r"(b[1]));
}
__device__ __forceinline__ void ldm4(uint32_t* r, uint32_t addr) {
    asm volatile("ldmatrix.sync.aligned.m8n8.x4.shared.b16 {%0,%1,%2,%3}, [%4];"
                 : "=r"(r[0]), "=r"(r[1]), "=r"(r[2]), "=r"(r[3]) : "r"(addr));
}
__device__ __forceinline__ void cpasync16(uint32_t dst, const void* src) {
    asm volatile("cp.async.cg.shared.global [%0], [%1], 16;" :: "r"(dst), "l"(src));
}
__device__ __forceinline__ void bf_split(float v, __nv_bfloat16& hi, __nv_bfloat16& lo) {
    hi = __float2bfloat16(v);
    lo = __float2bfloat16(v - __bfloat162float(hi));
}
__device__ __forceinline__ uint32_t pack_bf(__nv_bfloat16 a, __nv_bfloat16 b) {
    return (uint32_t)__bfloat16_as_ushort(a) | ((uint32_t)__bfloat16_as_ushort(b) << 16);
}
__device__ __forceinline__ uint32_t pack_hi2(float a, float b) {
    return pack_bf(__float2bfloat16(a), __float2bfloat16(b));
}
__device__ __forceinline__ uint32_t pack_lo2(float a, float b) {
    __nv_bfloat16 ha = __float2bfloat16(a), hb = __float2bfloat16(b);
    return pack_bf(__float2bfloat16(a - __bfloat162float(ha)),
                   __float2bfloat16(b - __bfloat162float(hb)));
}
__device__ __forceinline__ uint32_t pack4b(int a, int b, int c, int d) {
    return ((uint32_t)(uint8_t)a) | ((uint32_t)(uint8_t)b << 8)
         | ((uint32_t)(uint8_t)c << 16) | ((uint32_t)(uint8_t)d << 24);
}
// quantize v/s to two digits q = 128*qh + ql
__device__ __forceinline__ void quant2(float v, float inv_s, int& qh, int& ql) {
    int q = __float2int_rn(v * inv_s);
    qh = __float2int_rn((float)q * (1.0f / 128.0f));
    ql = q - (qh << 7);
}

// ===========================================================================
// prep_x: x fp32 -> two-digit int8 + per-row scale. 8 threads per row.
// ===========================================================================
__global__ void prep_x_kernel(const float* __restrict__ x)
{
    const int t = threadIdx.x;
    const int row = blockIdx.x * 32 + (t >> 3);
    const int c8 = t & 7;                 // 32 elements per thread

    const float* src = x + (size_t)row * 256 + c8 * 32;
    float4 f[8];
    float amax = 0.f;
#pragma unroll
    for (int i = 0; i < 8; i++) {
        f[i] = *(const float4*)(src + i * 4);
        amax = fmaxf(amax, fmaxf(fmaxf(fabsf(f[i].x), fabsf(f[i].y)),
                                 fmaxf(fabsf(f[i].z), fabsf(f[i].w))));
    }
#pragma unroll
    for (int off = 4; off; off >>= 1)
        amax = fmaxf(amax, __shfl_xor_sync(0xffffffffu, amax, off));
    float s = fmaxf(amax, 1e-30f) * (1.0f / 16128.0f);
    float inv_s = 1.0f / s;
    if (c8 == 0) g_sx[row] = s;

    uint32_t* dsth = (uint32_t*)(g_xq_hi + (size_t)row * 256 + c8 * 32);
    uint32_t* dstl = (uint32_t*)(g_xq_lo + (size_t)row * 256 + c8 * 32);
#pragma unroll
    for (int i = 0; i < 8; i++) {
        int h0, l0, h1, l1, h2, l2, h3, l3;
        quant2(f[i].x, inv_s, h0, l0);
        quant2(f[i].y, inv_s, h1, l1);
        quant2(f[i].z, inv_s, h2, l2);
        quant2(f[i].w, inv_s, h3, l3);
        dsth[i] = pack4b(h0, h1, h2, h3);
        dstl[i] = pack4b(l0, l1, l2, l3);
    }
}

// ===========================================================================
// prep_w: qkv weights -> two-digit int8 [n][k] + scales; proj -> bf16 hi/lo;
// qkv bias pack.
// ===========================================================================
__global__ void prep_w_kernel(const float* __restrict__ qkv_w,
                              const float* __restrict__ proj_w,
                              const float* __restrict__ q_bias,
                              const float* __restrict__ v_bias)
{
    int gid = blockIdx.x * blockDim.x + threadIdx.x;
    int gsz = gridDim.x * blockDim.x;

    if (gid < 768) {
        const int n = gid;
        float amax = 0.f;
        for (int k = 0; k < 256; k++)
            amax = fmaxf(amax, fabsf(qkv_w[(size_t)k * 768 + n]));
        float s = fmaxf(amax, 1e-30f) * (1.0f / 16128.0f);
        float inv_s = 1.0f / s;
        g_swq[n] = s;
        for (int k = 0; k < 256; k += 4) {
            int h[4], l[4];
#pragma unroll
            for (int j = 0; j < 4; j++)
                quant2(qkv_w[(size_t)(k + j) * 768 + n], inv_s, h[j], l[j]);
            *(uint32_t*)(g_wq_hi + (size_t)n * 256 + k) = pack4b(h[0], h[1], h[2], h[3]);
            *(uint32_t*)(g_wq_lo + (size_t)n * 256 + k) = pack4b(l[0], l[1], l[2], l[3]);
        }
    }
    for (int i = gid; i < 256 * 256; i += gsz) {
        int n = i >> 8, k = i & 255;
        __nv_bfloat16 hi, lo;
        bf_split(proj_w[(size_t)k * 256 + n], hi, lo);
        g_wproj_hi[i] = hi; g_wproj_lo[i] = lo;
    }
    for (int i = gid; i < 768; i += gsz)
        g_bias_qkv[i] = (i < 256) ? q_bias[i] : ((i < 512) ? 0.f : v_bias[i - 512]);
}

// ===========================================================================
// cpb: continuous position bias (window-independent)
// ===========================================================================
__global__ void cpb_kernel(const float* __restrict__ coords_table,
                           const float* __restrict__ mlp1_w,
                           const float* __restrict__ mlp1_b,
                           const float* __restrict__ mlp2_w,
                           const int*   __restrict__ rel_pos_index)
{
    __shared__ float bt[225 * 8];
    int t = threadIdx.x;
    if (t < 225) {
        float c0 = coords_table[t * 2 + 0];
        float c1 = coords_table[t * 2 + 1];
        float acc[8];
#pragma unroll
        for (int hh = 0; hh < 8; hh++) acc[hh] = 0.f;
        for (int k = 0; k < 512; k++) {
            float hv = fmaxf(c0 * mlp1_w[k] + c1 * mlp1_w[512 + k] + mlp1_b[k], 0.f);
#pragma unroll
            for (int hh = 0; hh < 8; hh++) acc[hh] += hv * mlp2_w[k * 8 + hh];
        }
#pragma unroll
        for (int hh = 0; hh < 8; hh++) bt[t * 8 + hh] = acc[hh];
    }
    __syncthreads();
    for (int idx = t; idx < 8 * 64 * 64; idx += blockDim.x) {
        int hh = idx >> 12;
        int ij = idx & 4095;
        float v = bt[rel_pos_index[ij] * 8 + hh];
        g_rel_bias[idx] = 16.f / (1.f + __expf(-v));
    }
}

// ===========================================================================
// gemm_qkv (int8 two-digit): C[128,64] CTA tile, k64-byte chunks, cp.async
// double buffer. 8 warps (4m x 2n), warp tile 32x32, dual s32 accumulators.
// grid (12, 1024): ntile fastest -> A L2-shared across 12 ntiles.
// out = sx[m]*swq[n]*(16384*acc_hh + 128*acc_mid) + bias -> g_qkv fp32.
// ===========================================================================
#define LDQ 80                          // staged row stride (bytes): 64 + 16
#define A_CHQ (128 * LDQ)               // 10240
#define B_CHQ (64 * LDQ)                // 5120
#define BUFQ  (2 * A_CHQ + 2 * B_CHQ)   // 30720
#define SMEMQ (2 * BUFQ)                // 61440

__global__ void __launch_bounds__(256, 2)
gemm_qkv_kernel()
{
    extern __shared__ char smq[];
    const uint32_t sb = smem_u32(smq);

    const int t = threadIdx.x, lane = t & 31, w = t >> 5;
    const int wm = w & 3, wn = w >> 2;
    const int ntile = blockIdx.x, mtile = blockIdx.y;   // ntile: 64-col group

    const size_t aoff = (size_t)mtile * 128 * 256;      // bytes
    const size_t boff = (size_t)ntile * 64 * 256;

    auto stage = [&](int s, int buf) {
        const int k0 = s * 64;
        const uint32_t AH = sb + buf * BUFQ;
        const uint32_t AL = AH + A_CHQ;
        const uint32_t BH = AL + A_CHQ;
        const uint32_t BL = BH + B_CHQ;
        // A: 128 rows x 64 B = 512 x 16B per digit
#pragma unroll
        for (int rep = 0; rep < 2; rep++) {
            int idx = rep * 256 + t;
            int row = idx >> 2, cg = idx & 3;
            uint32_t so = (uint32_t)(row * LDQ + cg * 16);
            size_t go = (size_t)row * 256 + k0 + cg * 16;
            cpasync16(AH + so, g_xq_hi + aoff + go);
            cpasync16(AL + so, g_xq_lo + aoff + go);
        }
        // B: 64 rows x 64 B = 256 x 16B per digit
        {
            int row = t >> 2, cg = t & 3;
            uint32_t so = (uint32_t)(row * LDQ + cg * 16);
            size_t go = boff + (size_t)row * 256 + k0 + cg * 16;
            cpasync16(BH + so, g_wq_hi + go);
            cpasync16(BL + so, g_wq_lo + go);
        }
        asm volatile("cp.async.commit_group;" ::: "memory");
    };

    int acc_hh[2][4][4], acc_md[2][4][4];
#pragma unroll
    for (int mi = 0; mi < 2; mi++)
#pragma unroll
        for (int n8 = 0; n8 < 4; n8++)
#pragma unroll
            for (int r = 0; r < 4; r++) { acc_hh[mi][n8][r] = 0; acc_md[mi][n8][r] = 0; }

    stage(0, 0);
    stage(1, 1);

    const int quad = lane >> 3, l8 = lane & 7;

    for (int s = 0; s < 4; s++) {
        if (s < 3) asm volatile("cp.async.wait_group 1;" ::: "memory");
        else       asm volatile("cp.async.wait_group 0;" ::: "memory");
        __syncthreads();

        const uint32_t AH = sb + (s & 1) * BUFQ;
        const uint32_t AL = AH + A_CHQ;
        const uint32_t BH = AL + A_CHQ;
        const uint32_t BL = BH + B_CHQ;

#pragma unroll
        for (int ks = 0; ks < 2; ks++) {           // k32-byte steps
            uint32_t ah[2][4], al[2][4];
            {
                int arow = wm * 32 + (lane & 15);
                uint32_t ao = (uint32_t)(arow * LDQ + ks * 32 + ((lane >> 4) << 4));
                ldm4(ah[0], AH + ao);
                ldm4(ah[1], AH + ao + 16 * LDQ);
                ldm4(al[0], AL + ao);
                ldm4(al[1], AL + ao + 16 * LDQ);
            }
#pragma unroll
            for (int np = 0; np < 2; np++) {
                int brow = wn * 32 + np * 16 + ((quad >> 1) << 3) + l8;
                uint32_t bo = (uint32_t)(brow * LDQ + ks * 32 + ((quad & 1) << 4));
                uint32_t bqh[4], bql[4];
                ldm4(bqh, BH + bo);
                ldm4(bql, BL + bo);
#pragma unroll
                for (int mi = 0; mi < 2; mi++) {
                    mma_s8(acc_hh[mi][2 * np + 0], ah[mi], bqh + 0);   // hh
                    mma_s8(acc_hh[mi][2 * np + 1], ah[mi], bqh + 2);
                    mma_s8(acc_md[mi][2 * np + 0], ah[mi], bql + 0);   // h*l
                    mma_s8(acc_md[mi][2 * np + 1], ah[mi], bql + 2);
                    mma_s8(acc_md[mi][2 * np + 0], al[mi], bqh + 0);   // l*h
                    mma_s8(acc_md[mi][2 * np + 1], al[mi], bqh + 2);
                }
            }
        }
        __syncthreads();
        if (s + 2 < 4) stage(s + 2, s & 1);
    }

    // ---- epilogue: dequant + bias, scatter fp32 to g_qkv ------------------------
    const int row_l = wm * 32 + (lane >> 2);
    const int col_l = wn * 32 + (lane & 3) * 2;
#pragma unroll
    for (int mi = 0; mi < 2; mi++) {
#pragma unroll
        for (int n8 = 0; n8 < 4; n8++) {
            int gc = ntile * 64 + col_l + n8 * 8;
            int sec = gc >> 8, hh2 = (gc >> 5) & 7, d = gc & 31;
            float sw0 = g_swq[gc], sw1 = g_swq[gc + 1];
            float b0 = g_bias_qkv[gc], b1 = g_bias_qkv[gc + 1];
#pragma unroll
            for (int half = 0; half < 2; half++) {
                int row = mtile * 128 + row_l + mi * 16 + half * 8;
                float sx = g_sx[row];
                int win = row >> 6, tok = row & 63;
                size_t addr = (((size_t)sec * 2048 + win) * 8 + hh2) * 2048
                              + (size_t)tok * 32 + d;
                float v0 = sx * sw0 * (16384.f * (float)acc_hh[mi][n8][2 * half + 0]
                                       + 128.f * (float)acc_md[mi][n8][2 * half + 0]) + b0;
                float v1 = sx * sw1 * (16384.f * (float)acc_hh[mi][n8][2 * half + 1]
                                       + 128.f * (float)acc_md[mi][n8][2 * half + 1]) + b1;
                *(float2*)&g_qkv[addr] = make_float2(v0, v1);
            }
        }
    }
}

// ===========================================================================
// attnproj: fused attention + proj (identical to proven R13 version).
// ===========================================================================
#define LQ 40    // q/k hi/lo row stride (bf16)
#define LV 72    // VT row stride (bf16)
#define LWB 136  // proj B stage row stride (bf16)
#define LRED 36

#define GRP_BYTES 29696

__global__ void __launch_bounds__(256, 2)
attnproj_kernel(const float* __restrict__ mask,
                const float* __restrict__ logit_scale,
                const float* __restrict__ proj_b,
                float*       __restrict__ out)
{
    __shared__ __align__(16) char smraw[2 * GRP_BYTES];
    const uint32_t sb = smem_u32(smraw);

    const int t = threadIdx.x, lane = t & 31, w = t >> 5;
    const int g = w >> 2, wm = w & 3, tg = t & 127;
    const int win = blockIdx.x;
    const int quad = lane >> 3, l8 = lane & 7;

    const uint32_t gb = sb + g * GRP_BYTES;
    const uint32_t uQH = gb, uQL = gb + 5120, uKH = gb + 10240, uKL = gb + 15360;
    const uint32_t uVH = gb + 20480, uVL = gb + 25088;
    __nv_bfloat16* VTH = (__nv_bfloat16*)(smraw + g * GRP_BYTES + 20480);
    __nv_bfloat16* VTL = (__nv_bfloat16*)(smraw + g * GRP_BYTES + 25088);

    uint32_t cxh[4][8], cxl[4][8];

    for (int it = 0; it < 4; it++) {
        const int h = g * 4 + it;
        const float* qg = g_qkv + (((size_t)0 * 2048 + win) * 8 + h) * 2048;
        const float* kg = g_qkv + (((size_t)1 * 2048 + win) * 8 + h) * 2048;
        const float* vg = g_qkv + (((size_t)2 * 2048 + win) * 8 + h) * 2048;

#pragma unroll
        for (int rep = 0; rep < 4; rep++) {
            int idx = rep * 128 + tg;
            int tok = idx >> 3, d4 = (idx & 7) * 4;
            float4 fv = *(const float4*)(vg + idx * 4);
            float vv[4] = {fv.x, fv.y, fv.z, fv.w};
#pragma unroll
            for (int j = 0; j < 4; j++) {
                __nv_bfloat16 hi, lo;
                bf_split(vv[j], hi, lo);
                VTH[(d4 + j) * LV + tok] = hi;
                VTL[(d4 + j) * LV + tok] = lo;
            }
        }

        {
            int r = tg & 63;
            const float* src = (tg < 64) ? (qg + r * 32) : (kg + r * 32);
            float4 rv[8];
            float s = 0.f;
#pragma unroll
            for (int i = 0; i < 8; i++) {
                rv[i] = *(const float4*)(src + i * 4);
                s += rv[i].x * rv[i].x + rv[i].y * rv[i].y
                   + rv[i].z * rv[i].z + rv[i].w * rv[i].w;
            }
            float inv = rsqrtf(fmaxf(s, 1e-24f));
            if (tg < 64) inv *= __expf(fminf(logit_scale[h], 4.605170185988092f));
            uint32_t dh = ((tg < 64) ? uQH : uKH) + (uint32_t)(r * LQ) * 2;
            uint32_t dl = ((tg < 64) ? uQL : uKL) + (uint32_t)(r * LQ) * 2;
#pragma unroll
            for (int i = 0; i < 8; i++) {
                float v0 = rv[i].x * inv, v1 = rv[i].y * inv;
                float v2 = rv[i].z * inv, v3 = rv[i].w * inv;
                asm volatile("st.shared.v2.b32 [%0], {%1,%2};"
                             :: "r"(dh + i * 8), "r"(pack_hi2(v0, v1)), "r"(pack_hi2(v2, v3)));
                asm volatile("st.shared.v2.b32 [%0], {%1,%2};"
                             :: "r"(dl + i * 8), "r"(pack_lo2(v0, v1)), "r"(pack_lo2(v2, v3)));
            }
        }
        asm volatile("bar.sync %0, 128;" :: "r"(g + 1) : "memory");

        float acc[8][4];
#pragma unroll
        for (int n8 = 0; n8 < 8; n8++)
#pragma unroll
            for (int r = 0; r < 4; r++) acc[n8][r] = 0.f;

#pragma unroll
        for (int ks = 0; ks < 2; ks++) {
            uint32_t ah[4], al[4];
            {
                int arow = wm * 16 + (lane & 15);
                int acol = ks * 16 + ((lane >> 4) << 3);
                uint32_t ao = (uint32_t)(arow * LQ + acol) * 2;
                ldm4(ah, uQH + ao);
                ldm4(al, uQL + ao);
            }
            const int bcol = ks * 16 + ((quad & 1) << 3);
#pragma unroll
            for (int np = 0; np < 4; np++) {
                int brow = np * 16 + ((quad >> 1) << 3) + l8;
                uint32_t bo = (uint32_t)(brow * LQ + bcol) * 2;
                uint32_t bq[4];
                ldm4(bq, uKH + bo);
                mma_bf16(acc[2 * np + 0], ah, bq + 0);
                mma_bf16(acc[2 * np + 1], ah, bq + 2);
                mma_bf16(acc[2 * np + 0], al, bq + 0);
                mma_bf16(acc[2 * np + 1], al, bq + 2);
                ldm4(bq, uKL + bo);
                mma_bf16(acc[2 * np + 0], ah, bq + 0);
                mma_bf16(acc[2 * np + 1], ah, bq + 2);
            }
        }

        {
            const float* rb = g_rel_bias + h * 4096;
            const float* mk = mask + (size_t)(win & 255) * 4096;
            const int i0 = wm * 16 + (lane >> 2);
            const int i1 = i0 + 8;
            const int jc = (lane & 3) * 2;
#pragma unroll
            for (int n8 = 0; n8 < 8; n8++) {
                int o0 = i0 * 64 + n8 * 8 + jc;
                int o1 = i1 * 64 + n8 * 8 + jc;
                float2 r0 = *(const float2*)(rb + o0), m0 = *(const float2*)(mk + o0);
                float2 r1 = *(const float2*)(rb + o1), m1 = *(const float2*)(mk + o1);
                acc[n8][0] += r0.x + m0.x;  acc[n8][1] += r0.y + m0.y;
                acc[n8][2] += r1.x + m1.x;  acc[n8][3] += r1.y + m1.y;
            }
            float mx0 = -1e30f, mx1 = -1e30f;
#pragma unroll
            for (int n8 = 0; n8 < 8; n8++) {
                mx0 = fmaxf(mx0, fmaxf(acc[n8][0], acc[n8][1]));
                mx1 = fmaxf(mx1, fmaxf(acc[n8][2], acc[n8][3]));
            }
            mx0 = fmaxf(mx0, __shfl_xor_sync(0xffffffffu, mx0, 1));
            mx0 = fmaxf(mx0, __shfl_xor_sync(0xffffffffu, mx0, 2));
            mx1 = fmaxf(mx1, __shfl_xor_sync(0xffffffffu, mx1, 1));
            mx1 = fmaxf(mx1, __shfl_xor_sync(0xffffffffu, mx1, 2));
            float s0 = 0.f, s1 = 0.f;
#pragma unroll
            for (int n8 = 0; n8 < 8; n8++) {
                acc[n8][0] = __expf(acc[n8][0] - mx0);
                acc[n8][1] = __expf(acc[n8][1] - mx0);
                acc[n8][2] = __expf(acc[n8][2] - mx1);
                acc[n8][3] = __expf(acc[n8][3] - mx1);
                s0 += acc[n8][0] + acc[n8][1];
                s1 += acc[n8][2] + acc[n8][3];
            }
            s0 += __shfl_xor_sync(0xffffffffu, s0, 1);
            s0 += __shfl_xor_sync(0xffffffffu, s0, 2);
            s1 += __shfl_xor_sync(0xffffffffu, s1, 1);
            s1 += __shfl_xor_sync(0xffffffffu, s1, 2);
            float inv0 = 1.f / s0, inv1 = 1.f / s1;
#pragma unroll
            for (int n8 = 0; n8 < 8; n8++) {
                acc[n8][0] *= inv0;  acc[n8][1] *= inv0;
                acc[n8][2] *= inv1;  acc[n8][3] *= inv1;
            }
        }

        float acc2[4][4];
#pragma unroll
        for (int n8 = 0; n8 < 4; n8++)
#pragma unroll
            for (int r = 0; r < 4; r++) acc2[n8][r] = 0.f;

#pragma unroll
        for (int ks = 0; ks < 4; ks++) {
            uint32_t ph[4], pl[4];
            ph[0] = pack_hi2(acc[2 * ks][0],     acc[2 * ks][1]);
            ph[1] = pack_hi2(acc[2 * ks][2],     acc[2 * ks][3]);
            ph[2] = pack_hi2(acc[2 * ks + 1][0], acc[2 * ks + 1][1]);
            ph[3] = pack_hi2(acc[2 * ks + 1][2], acc[2 * ks + 1][3]);
            pl[0] = pack_lo2(acc[2 * ks][0],     acc[2 * ks][1]);
            pl[1] = pack_lo2(acc[2 * ks][2],     acc[2 * ks][3]);
            pl[2] = pack_lo2(acc[2 * ks + 1][0], acc[2 * ks + 1][1]);
            pl[3] = pack_lo2(acc[2 * ks + 1][2], acc[2 * ks + 1][3]);

            const int bcol = ks * 16 + ((quad & 1) << 3);
#pragma unroll
            for (int np = 0; np < 2; np++) {
                int brow = np * 16 + ((quad >> 1) << 3) + l8;
                uint32_t bo = (uint32_t)(brow * LV + bcol) * 2;
                uint32_t bq[4];
                ldm4(bq, uVH + bo);
                mma_bf16(acc2[2 * np + 0], ph, bq + 0);
                mma_bf16(acc2[2 * np + 1], ph, bq + 2);
                mma_bf16(acc2[2 * np + 0], pl, bq + 0);
                mma_bf16(acc2[2 * np + 1], pl, bq + 2);
                ldm4(bq, uVL + bo);
                mma_bf16(acc2[2 * np + 0], ph, bq + 0);
                mma_bf16(acc2[2 * np + 1], ph, bq + 2);
            }
        }

#pragma unroll
        for (int kf = 0; kf < 2; kf++) {
            cxh[it][kf * 4 + 0] = pack_hi2(acc2[2 * kf][0],     acc2[2 * kf][1]);
            cxh[it][kf * 4 + 1] = pack_hi2(acc2[2 * kf][2],     acc2[2 * kf][3]);
            cxh[it][kf * 4 + 2] = pack_hi2(acc2[2 * kf + 1][0], acc2[2 * kf + 1][1]);
            cxh[it][kf * 4 + 3] = pack_hi2(acc2[2 * kf + 1][2], acc2[2 * kf + 1][3]);
            cxl[it][kf * 4 + 0] = pack_lo2(acc2[2 * kf][0],     acc2[2 * kf][1]);
            cxl[it][kf * 4 + 1] = pack_lo2(acc2[2 * kf][2],     acc2[2 * kf][3]);
            cxl[it][kf * 4 + 2] = pack_lo2(acc2[2 * kf + 1][0], acc2[2 * kf + 1][1]);
            cxl[it][kf * 4 + 3] = pack_lo2(acc2[2 * kf + 1][2], acc2[2 * kf + 1][3]);
        }
        asm volatile("bar.sync %0, 128;" :: "r"(g + 1) : "memory");
    }

    __syncthreads();

    const uint32_t uWBH = sb + g * 17408;
    const uint32_t uWBL = uWBH + 8704;
    float* RED = (float*)(smraw + 2 * 17408);

    for (int p = 0; p < 8; p++) {
#pragma unroll
        for (int rep = 0; rep < 4; rep++) {
            int idx = rep * 128 + tg;
            int row = idx >> 4, cg = idx & 15;
            uint32_t so = (uint32_t)(row * LWB + cg * 8) * 2;
            size_t go = (size_t)(p * 32 + row) * 256 + g * 128 + cg * 8;
            cpasync16(uWBH + so, g_wproj_hi + go);
            cpasync16(uWBL + so, g_wproj_lo + go);
        }
        asm volatile("cp.async.commit_group;" ::: "memory");
        asm volatile("cp.async.wait_group 0;" ::: "memory");
        asm volatile("bar.sync %0, 128;" :: "r"(g + 1) : "memory");

        float pacc[4][4];
#pragma unroll
        for (int n8 = 0; n8 < 4; n8++)
#pragma unroll
            for (int r = 0; r < 4; r++) pacc[n8][r] = 0.f;

#pragma unroll
        for (int it = 0; it < 4; it++) {
#pragma unroll
            for (int kf = 0; kf < 2; kf++) {
                const int bcol = it * 32 + kf * 16 + ((quad & 1) << 3);
#pragma unroll
                for (int np = 0; np < 2; np++) {
                    int brow = np * 16 + ((quad >> 1) << 3) + l8;
                    uint32_t bo = (uint32_t)(brow * LWB + bcol) * 2;
                    uint32_t bq[4];
                    ldm4(bq, uWBH + bo);
                    mma_bf16(pacc[2 * np + 0], &cxh[it][kf * 4], bq + 0);
                    mma_bf16(pacc[2 * np + 1], &cxh[it][kf * 4], bq + 2);
                    mma_bf16(pacc[2 * np + 0], &cxl[it][kf * 4], bq + 0);
                    mma_bf16(pacc[2 * np + 1], &cxl[it][kf * 4], bq + 2);
                    ldm4(bq, uWBL + bo);
                    mma_bf16(pacc[2 * np + 0], &cxh[it][kf * 4], bq + 0);
                    mma_bf16(pacc[2 * np + 1], &cxh[it][kf * 4], bq + 2);
                }
            }
        }

        const int r0 = wm * 16 + (lane >> 2);
        const int c2 = (lane & 3) * 2;
        if (g == 1) {
#pragma unroll
            for (int n8 = 0; n8 < 4; n8++) {
                *(float2*)&RED[r0 * LRED + n8 * 8 + c2]       = make_float2(pacc[n8][0], pacc[n8][1]);
                *(float2*)&RED[(r0 + 8) * LRED + n8 * 8 + c2] = make_float2(pacc[n8][2], pacc[n8][3]);
            }
        }
        __syncthreads();
        if (g == 0) {
#pragma unroll
            for (int n8 = 0; n8 < 4; n8++) {
                int gc = p * 32 + n8 * 8 + c2;
                float b0 = proj_b[gc], b1 = proj_b[gc + 1];
                float2 q0 = *(const float2*)&RED[r0 * LRED + n8 * 8 + c2];
                float2 q1 = *(const float2*)&RED[(r0 + 8) * LRED + n8 * 8 + c2];
                float2 v0 = make_float2(pacc[n8][0] + q0.x + b0, pacc[n8][1] + q0.y + b1);
                float2 v1 = make_float2(pacc[n8][2] + q1.x + b0, pacc[n8][3] + q1.y + b1);
                *(float2*)&out[((size_t)win * 64 + r0) * 256 + gc]     = v0;
                *(float2*)&out[((size_t)win * 64 + r0 + 8) * 256 + gc] = v1;
            }
        }
        __syncthreads();
    }
}

// ===========================================================================
extern "C" void kernel_launch(void* const* d_in, const int* in_sizes, int n_in,
                              void* d_out, int out_size)
{
    const float* x            = (const float*)d_in[0];
    const float* mask         = (const float*)d_in[1];
    const float* qkv_w        = (const float*)d_in[2];
    const float* q_bias       = (const float*)d_in[3];
    const float* v_bias       = (const float*)d_in[4];
    const float* logit_scale  = (const float*)d_in[5];
    const float* coords_table = (const float*)d_in[6];
    const float* mlp1_w       = (const float*)d_in[7];
    const float* mlp1_b       = (const float*)d_in[8];
    const float* mlp2_w       = (const float*)d_in[9];
    const float* proj_w       = (const float*)d_in[10];
    const float* proj_b       = (const float*)d_in[11];
    const int*   rel_pos_idx  = (const int*)d_in[12];
    float* out = (float*)d_out;

    cudaFuncSetAttribute(gemm_qkv_kernel,
                         cudaFuncAttributeMaxDynamicSharedMemorySize, SMEMQ);

    prep_x_kernel<<<4096, 256>>>(x);
    prep_w_kernel<<<256, 256>>>(qkv_w, proj_w, q_bias, v_bias);
    cpb_kernel<<<1, 256>>>(coords_table, mlp1_w, mlp1_b, mlp2_w, rel_pos_idx);
    gemm_qkv_kernel<<<dim3(12, 1024), 256, SMEMQ>>>();
    attnproj_kernel<<<2048, 256>>>(mask, logit_scale, proj_b, out);
}

// round 15
// speedup vs baseline: 1.6436x; 1.6436x over previous
#include <cuda_runtime.h>
#include <cuda_bf16.h>
#include <cstdint>
#include <math.h>

// ===========================================================================
// WindowAttentionV2: split-bf16 mma.sync; fused attention+proj (ctx in regs).
// R13 base + double-buffered proj staging + packed V-transpose stores.
// B=2048 win, N=64 tok, C=256, H=8, D=32.
// ===========================================================================

// ---- device scratch --------------------------------------------------------
__device__ float g_qkv[3u * 2048 * 8 * 2048];          // [(sec*2048+win)*8+h][tok*32+d]
__device__ __nv_bfloat16 g_xhi[131072u * 256];
__device__ __nv_bfloat16 g_xlo[131072u * 256];
__device__ __nv_bfloat16 g_wqkv_hi[768 * 256];         // [n][k]
__device__ __nv_bfloat16 g_wqkv_lo[768 * 256];
__device__ __nv_bfloat16 g_wproj_hi[256 * 256];
__device__ __nv_bfloat16 g_wproj_lo[256 * 256];
__device__ float g_rel_bias[8 * 64 * 64];
__device__ float g_bias_qkv[768];

// ---- helpers ----------------------------------------------------------------
__device__ __forceinline__ uint32_t smem_u32(const void* p) {
    uint32_t a;
    asm("{ .reg .u64 t; cvta.to.shared.u64 t, %1; cvt.u32.u64 %0, t; }"
        : "=r"(a) : "l"(p));
    return a;
}
__device__ __forceinline__ void mma_bf16(float* c, const uint32_t* a, const uint32_t* b) {
    asm volatile(
        "mma.sync.aligned.m16n8k16.row.col.f32.bf16.bf16.f32 "
        "{%0,%1,%2,%3}, {%4,%5,%6,%7}, {%8,%9}, {%0,%1,%2,%3};"
        : "+f"(c[0]), "+f"(c[1]), "+f"(c[2]), "+f"(c[3])
        : "r"(a[0]), "r"(a[1]), "r"(a[2]), "r"(a[3]), "r"(b[0]), "r"(b[1]));
}
__device__ __forceinline__ void ldm4(uint32_t* r, uint32_t addr) {
    asm volatile("ldmatrix.sync.aligned.m8n8.x4.shared.b16 {%0,%1,%2,%3}, [%4];"
                 : "=r"(r[0]), "=r"(r[1]), "=r"(r[2]), "=r"(r[3]) : "r"(addr));
}
__device__ __forceinline__ void cpasync16(uint32_t dst, const void* src) {
    asm volatile("cp.async.cg.shared.global [%0], [%1], 16;" :: "r"(dst), "l"(src));
}
__device__ __forceinline__ void bf_split(float v, __nv_bfloat16& hi, __nv_bfloat16& lo) {
    hi = __float2bfloat16(v);
    lo = __float2bfloat16(v - __bfloat162float(hi));
}
__device__ __forceinline__ uint32_t pack_bf(__nv_bfloat16 a, __nv_bfloat16 b) {
    return (uint32_t)__bfloat16_as_ushort(a) | ((uint32_t)__bfloat16_as_ushort(b) << 16);
}
__device__ __forceinline__ uint32_t pack_hi2(float a, float b) {
    return pack_bf(__float2bfloat16(a), __float2bfloat16(b));
}
__device__ __forceinline__ uint32_t pack_lo2(float a, float b) {
    __nv_bfloat16 ha = __float2bfloat16(a), hb = __float2bfloat16(b);
    return pack_bf(__float2bfloat16(a - __bfloat162float(ha)),
                   __float2bfloat16(b - __bfloat162float(hb)));
}

// ===========================================================================
// prep_x: x fp32 -> bf16 hi/lo
// ===========================================================================
__global__ void prep_x_kernel(const float* __restrict__ x)
{
    int gid = blockIdx.x * blockDim.x + threadIdx.x;
    int gsz = gridDim.x * blockDim.x;
    for (int i = gid; i < 131072 * 64; i += gsz) {
        float4 f = ((const float4*)x)[i];
        __nv_bfloat16 h0, h1, h2, h3, l0, l1, l2, l3;
        bf_split(f.x, h0, l0); bf_split(f.y, h1, l1);
        bf_split(f.z, h2, l2); bf_split(f.w, h3, l3);
        ((__nv_bfloat162*)g_xhi)[2 * i]     = __nv_bfloat162(h0, h1);
        ((__nv_bfloat162*)g_xhi)[2 * i + 1] = __nv_bfloat162(h2, h3);
        ((__nv_bfloat162*)g_xlo)[2 * i]     = __nv_bfloat162(l0, l1);
        ((__nv_bfloat162*)g_xlo)[2 * i + 1] = __nv_bfloat162(l2, l3);
    }
}

// ===========================================================================
// prep_w: weights -> [n][k] bf16 hi/lo, qkv bias pack
// ===========================================================================
__global__ void prep_w_kernel(const float* __restrict__ qkv_w,
                              const float* __restrict__ proj_w,
                              const float* __restrict__ q_bias,
                              const float* __restrict__ v_bias)
{
    int gid = blockIdx.x * blockDim.x + threadIdx.x;
    int gsz = gridDim.x * blockDim.x;
    for (int i = gid; i < 768 * 256; i += gsz) {
        int n = i >> 8, k = i & 255;
        __nv_bfloat16 hi, lo;
        bf_split(qkv_w[(size_t)k * 768 + n], hi, lo);
        g_wqkv_hi[i] = hi; g_wqkv_lo[i] = lo;
    }
    for (int i = gid; i < 256 * 256; i += gsz) {
        int n = i >> 8, k = i & 255;
        __nv_bfloat16 hi, lo;
        bf_split(proj_w[(size_t)k * 256 + n], hi, lo);
        g_wproj_hi[i] = hi; g_wproj_lo[i] = lo;
    }
    for (int i = gid; i < 768; i += gsz)
        g_bias_qkv[i] = (i < 256) ? q_bias[i] : ((i < 512) ? 0.f : v_bias[i - 512]);
}

// ===========================================================================
// cpb: continuous position bias (window-independent)
// ===========================================================================
__global__ void cpb_kernel(const float* __restrict__ coords_table,
                           const float* __restrict__ mlp1_w,
                           const float* __restrict__ mlp1_b,
                           const float* __restrict__ mlp2_w,
                           const int*   __restrict__ rel_pos_index)
{
    __shared__ float bt[225 * 8];
    int t = threadIdx.x;
    if (t < 225) {
        float c0 = coords_table[t * 2 + 0];
        float c1 = coords_table[t * 2 + 1];
        float acc[8];
#pragma unroll
        for (int hh = 0; hh < 8; hh++) acc[hh] = 0.f;
        for (int k = 0; k < 512; k++) {
            float hv = fmaxf(c0 * mlp1_w[k] + c1 * mlp1_w[512 + k] + mlp1_b[k], 0.f);
#pragma unroll
            for (int hh = 0; hh < 8; hh++) acc[hh] += hv * mlp2_w[k * 8 + hh];
        }
#pragma unroll
        for (int hh = 0; hh < 8; hh++) bt[t * 8 + hh] = acc[hh];
    }
    __syncthreads();
    for (int idx = t; idx < 8 * 64 * 64; idx += blockDim.x) {
        int hh = idx >> 12;
        int ij = idx & 4095;
        float v = bt[rel_pos_index[ij] * 8 + hh];
        g_rel_bias[idx] = 16.f / (1.f + __expf(-v));
    }
}

// ===========================================================================
// gemm_qkv: C[128,128] tile, split bf16, cp.async k32 double buffer.
// grid (6, 1024): ntile fastest -> A tile read once from DRAM, reused via L2.
// (identical to R13 — proven 437us)
// ===========================================================================
#define LDC 40
#define CH_B  (128 * LDC * 2)         // 10240
#define BUF_B (4 * CH_B)              // AH AL BH BL = 40960
#define SMEM_G (2 * BUF_B)            // 81920

__global__ void __launch_bounds__(256, 2)
gemm_qkv_kernel()
{
    extern __shared__ __nv_bfloat16 smb[];
    const uint32_t sb = smem_u32(smb);

    const int t = threadIdx.x, lane = t & 31, w = t >> 5;
    const int wm = w & 3, wn = w >> 2;
    const int ntile = blockIdx.x, mtile = blockIdx.y;

    const size_t aoff = (size_t)mtile * 128 * 256;
    const size_t boff = (size_t)ntile * 128 * 256;

    auto stage = [&](int s, int buf) {
        const int k0 = s * 32;
        const uint32_t AH = sb + buf * BUF_B;
        const uint32_t AL = AH + CH_B;
        const uint32_t BH = AL + CH_B;
        const uint32_t BL = BH + CH_B;
#pragma unroll
        for (int rep = 0; rep < 2; rep++) {
            int idx = rep * 256 + t;
            int row = idx >> 2, cg = idx & 3;
            uint32_t so = (uint32_t)(row * LDC + cg * 8) * 2;
            size_t go = (size_t)row * 256 + k0 + cg * 8;
            cpasync16(AH + so, g_xhi + aoff + go);
            cpasync16(AL + so, g_xlo + aoff + go);
            cpasync16(BH + so, g_wqkv_hi + boff + go);
            cpasync16(BL + so, g_wqkv_lo + boff + go);
        }
        asm volatile("cp.async.commit_group;" ::: "memory");
    };

    float acc[2][8][4];
#pragma unroll
    for (int mi = 0; mi < 2; mi++)
#pragma unroll
        for (int n8 = 0; n8 < 8; n8++)
#pragma unroll
            for (int r = 0; r < 4; r++) acc[mi][n8][r] = 0.f;

    stage(0, 0);
    stage(1, 1);

    const int quad = lane >> 3, l8 = lane & 7;
    const int brow_base = wn * 64 + ((quad >> 1) << 3) + l8;

    for (int s = 0; s < 8; s++) {
        if (s < 7) asm volatile("cp.async.wait_group 1;" ::: "memory");
        else       asm volatile("cp.async.wait_group 0;" ::: "memory");
        __syncthreads();

        const uint32_t AH = sb + (s & 1) * BUF_B;
        const uint32_t AL = AH + CH_B;
        const uint32_t BH = AL + CH_B;
        const uint32_t BL = BH + CH_B;

#pragma unroll
        for (int ks = 0; ks < 2; ks++) {
            uint32_t ah[2][4], al[2][4];
            {
                int arow = wm * 32 + (lane & 15);
                int acol = ks * 16 + ((lane >> 4) << 3);
                uint32_t ao = (uint32_t)(arow * LDC + acol) * 2;
                ldm4(ah[0], AH + ao);
                ldm4(ah[1], AH + ao + 16 * LDC * 2);
                ldm4(al[0], AL + ao);
                ldm4(al[1], AL + ao + 16 * LDC * 2);
            }
            const int bcol = ks * 16 + ((quad & 1) << 3);

            uint32_t bh[2][4], bl[2][4];
            {
                uint32_t bo = (uint32_t)(brow_base * LDC + bcol) * 2;
                ldm4(bh[0], BH + bo);
                ldm4(bl[0], BL + bo);
            }
#pragma unroll
            for (int np = 0; np < 4; np++) {
                const int cur = np & 1, nxt = cur ^ 1;
                if (np < 3) {
                    uint32_t bo = (uint32_t)((brow_base + (np + 1) * 16) * LDC + bcol) * 2;
                    ldm4(bh[nxt], BH + bo);
                    ldm4(bl[nxt], BL + bo);
                }
#pragma unroll
                for (int mi = 0; mi < 2; mi++) {
                    mma_bf16(acc[mi][2 * np + 0], ah[mi], bh[cur] + 0);
                    mma_bf16(acc[mi][2 * np + 1], ah[mi], bh[cur] + 2);
                    mma_bf16(acc[mi][2 * np + 0], al[mi], bh[cur] + 0);
                    mma_bf16(acc[mi][2 * np + 1], al[mi], bh[cur] + 2);
                    mma_bf16(acc[mi][2 * np + 0], ah[mi], bl[cur] + 0);
                    mma_bf16(acc[mi][2 * np + 1], ah[mi], bl[cur] + 2);
                }
            }
        }
        __syncthreads();
        if (s + 2 < 8) stage(s + 2, s & 1);
    }

    const int row_l = wm * 32 + (lane >> 2);
    const int col_l = wn * 64 + (lane & 3) * 2;
#pragma unroll
    for (int mi = 0; mi < 2; mi++) {
#pragma unroll
        for (int n8 = 0; n8 < 8; n8++) {
            int gc = ntile * 128 + col_l + n8 * 8;
            int sec = gc >> 8, hh = (gc >> 5) & 7, d = gc & 31;
            float b0 = g_bias_qkv[gc], b1 = g_bias_qkv[gc + 1];
#pragma unroll
            for (int half = 0; half < 2; half++) {
                int row = mtile * 128 + row_l + mi * 16 + half * 8;
                int win = row >> 6, tok = row & 63;
                size_t addr = (((size_t)sec * 2048 + win) * 8 + hh) * 2048
                              + (size_t)tok * 32 + d;
                float2 v;
                v.x = acc[mi][n8][2 * half + 0] + b0;
                v.y = acc[mi][n8][2 * half + 1] + b1;
                *(float2*)&g_qkv[addr] = v;
            }
        }
    }
}

// ===========================================================================
// attnproj: fused attention + proj. CTA = window, 256 thr = 2 groups x 4 warps.
// Packed VT stores; proj WB double-buffered (staging overlaps MMA+reduction).
// ===========================================================================
#define LQ 40    // q/k hi/lo row stride (bf16)
#define LV 72    // VT row stride (bf16)
#define LWB 136  // proj B stage row stride (bf16)
#define LRED 36

#define GRP_BYTES 29696      // per-group attn scratch
#define WBBUF 17408          // one proj WB buffer (hi 8704 + lo 8704)
#define SM_ATTN (2 * GRP_BYTES)              // 59392
#define SM_PROJ (4 * WBBUF + 64 * LRED * 4)  // 69632 + 9216 = 78848

__global__ void __launch_bounds__(256, 2)
attnproj_kernel(const float* __restrict__ mask,
                const float* __restrict__ logit_scale,
                const float* __restrict__ proj_b,
                float*       __restrict__ out)
{
    __shared__ __align__(16) char smraw[SM_PROJ];   // > SM_ATTN
    const uint32_t sb = smem_u32(smraw);

    const int t = threadIdx.x, lane = t & 31, w = t >> 5;
    const int g = w >> 2, wm = w & 3, tg = t & 127;
    const int win = blockIdx.x;
    const int quad = lane >> 3, l8 = lane & 7;

    const uint32_t gb = sb + g * GRP_BYTES;
    const uint32_t uQH = gb, uQL = gb + 5120, uKH = gb + 10240, uKL = gb + 15360;
    const uint32_t uVH = gb + 20480, uVL = gb + 25088;
    __nv_bfloat16* VTH = (__nv_bfloat16*)(smraw + g * GRP_BYTES + 20480);
    __nv_bfloat16* VTL = (__nv_bfloat16*)(smraw + g * GRP_BYTES + 25088);

    uint32_t cxh[4][8], cxl[4][8];

    // =================== attention: 4 heads per group =========================
    for (int it = 0; it < 4; it++) {
        const int h = g * 4 + it;
        const float* qg = g_qkv + (((size_t)0 * 2048 + win) * 8 + h) * 2048;
        const float* kg = g_qkv + (((size_t)1 * 2048 + win) * 8 + h) * 2048;
        const float* vg = g_qkv + (((size_t)2 * 2048 + win) * 8 + h) * 2048;

        // V -> VT hi/lo (transposed), two tokens per 32-bit store
#pragma unroll
        for (int rep = 0; rep < 2; rep++) {
            int idx = rep * 128 + tg;           // 0..255
            int tp = idx >> 3;                  // token pair 0..31
            int d4 = (idx & 7) * 4;
            float4 fa = *(const float4*)(vg + (2 * tp) * 32 + d4);
            float4 fb = *(const float4*)(vg + (2 * tp + 1) * 32 + d4);
            float av[4] = {fa.x, fa.y, fa.z, fa.w};
            float bv[4] = {fb.x, fb.y, fb.z, fb.w};
#pragma unroll
            for (int j = 0; j < 4; j++) {
                *(uint32_t*)(VTH + (d4 + j) * LV + 2 * tp) = pack_hi2(av[j], bv[j]);
                *(uint32_t*)(VTL + (d4 + j) * LV + 2 * tp) = pack_lo2(av[j], bv[j]);
            }
        }

        // q/k per-thread row normalize straight from gmem
        {
            int r = tg & 63;
            const float* src = (tg < 64) ? (qg + r * 32) : (kg + r * 32);
            float4 rv[8];
            float s = 0.f;
#pragma unroll
            for (int i = 0; i < 8; i++) {
                rv[i] = *(const float4*)(src + i * 4);
                s += rv[i].x * rv[i].x + rv[i].y * rv[i].y
                   + rv[i].z * rv[i].z + rv[i].w * rv[i].w;
            }
            float inv = rsqrtf(fmaxf(s, 1e-24f));
            if (tg < 64) inv *= __expf(fminf(logit_scale[h], 4.605170185988092f));
            uint32_t dh = ((tg < 64) ? uQH : uKH) + (uint32_t)(r * LQ) * 2;
            uint32_t dl = ((tg < 64) ? uQL : uKL) + (uint32_t)(r * LQ) * 2;
#pragma unroll
            for (int i = 0; i < 8; i++) {
                float v0 = rv[i].x * inv, v1 = rv[i].y * inv;
                float v2 = rv[i].z * inv, v3 = rv[i].w * inv;
                asm volatile("st.shared.v2.b32 [%0], {%1,%2};"
                             :: "r"(dh + i * 8), "r"(pack_hi2(v0, v1)), "r"(pack_hi2(v2, v3)));
                asm volatile("st.shared.v2.b32 [%0], {%1,%2};"
                             :: "r"(dl + i * 8), "r"(pack_lo2(v0, v1)), "r"(pack_lo2(v2, v3)));
            }
        }
        asm volatile("bar.sync %0, 128;" :: "r"(g + 1) : "memory");

        // QK^T
        float acc[8][4];
#pragma unroll
        for (int n8 = 0; n8 < 8; n8++)
#pragma unroll
            for (int r = 0; r < 4; r++) acc[n8][r] = 0.f;

#pragma unroll
        for (int ks = 0; ks < 2; ks++) {
            uint32_t ah[4], al[4];
            {
                int arow = wm * 16 + (lane & 15);
                int acol = ks * 16 + ((lane >> 4) << 3);
                uint32_t ao = (uint32_t)(arow * LQ + acol) * 2;
                ldm4(ah, uQH + ao);
                ldm4(al, uQL + ao);
            }
            const int bcol = ks * 16 + ((quad & 1) << 3);
#pragma unroll
            for (int np = 0; np < 4; np++) {
                int brow = np * 16 + ((quad >> 1) << 3) + l8;
                uint32_t bo = (uint32_t)(brow * LQ + bcol) * 2;
                uint32_t bq[4];
                ldm4(bq, uKH + bo);
                mma_bf16(acc[2 * np + 0], ah, bq + 0);
                mma_bf16(acc[2 * np + 1], ah, bq + 2);
                mma_bf16(acc[2 * np + 0], al, bq + 0);
                mma_bf16(acc[2 * np + 1], al, bq + 2);
                ldm4(bq, uKL + bo);
                mma_bf16(acc[2 * np + 0], ah, bq + 0);
                mma_bf16(acc[2 * np + 1], ah, bq + 2);
            }
        }

        // + rel_bias + mask, softmax on fragments
        {
            const float* rb = g_rel_bias + h * 4096;
            const float* mk = mask + (size_t)(win & 255) * 4096;
            const int i0 = wm * 16 + (lane >> 2);
            const int i1 = i0 + 8;
            const int jc = (lane & 3) * 2;
#pragma unroll
            for (int n8 = 0; n8 < 8; n8++) {
                int o0 = i0 * 64 + n8 * 8 + jc;
                int o1 = i1 * 64 + n8 * 8 + jc;
                float2 r0 = *(const float2*)(rb + o0), m0 = *(const float2*)(mk + o0);
                float2 r1 = *(const float2*)(rb + o1), m1 = *(const float2*)(mk + o1);
                acc[n8][0] += r0.x + m0.x;  acc[n8][1] += r0.y + m0.y;
                acc[n8][2] += r1.x + m1.x;  acc[n8][3] += r1.y + m1.y;
            }
            float mx0 = -1e30f, mx1 = -1e30f;
#pragma unroll
            for (int n8 = 0; n8 < 8; n8++) {
                mx0 = fmaxf(mx0, fmaxf(acc[n8][0], acc[n8][1]));
                mx1 = fmaxf(mx1, fmaxf(acc[n8][2], acc[n8][3]));
            }
            mx0 = fmaxf(mx0, __shfl_xor_sync(0xffffffffu, mx0, 1));
            mx0 = fmaxf(mx0, __shfl_xor_sync(0xffffffffu, mx0, 2));
            mx1 = fmaxf(mx1, __shfl_xor_sync(0xffffffffu, mx1, 1));
            mx1 = fmaxf(mx1, __shfl_xor_sync(0xffffffffu, mx1, 2));
            float s0 = 0.f, s1 = 0.f;
#pragma unroll
            for (int n8 = 0; n8 < 8; n8++) {
                acc[n8][0] = __expf(acc[n8][0] - mx0);
                acc[n8][1] = __expf(acc[n8][1] - mx0);
                acc[n8][2] = __expf(acc[n8][2] - mx1);
                acc[n8][3] = __expf(acc[n8][3] - mx1);
                s0 += acc[n8][0] + acc[n8][1];
                s1 += acc[n8][2] + acc[n8][3];
            }
            s0 += __shfl_xor_sync(0xffffffffu, s0, 1);
            s0 += __shfl_xor_sync(0xffffffffu, s0, 2);
            s1 += __shfl_xor_sync(0xffffffffu, s1, 1);
            s1 += __shfl_xor_sync(0xffffffffu, s1, 2);
            float inv0 = 1.f / s0, inv1 = 1.f / s1;
#pragma unroll
            for (int n8 = 0; n8 < 8; n8++) {
                acc[n8][0] *= inv0;  acc[n8][1] *= inv0;
                acc[n8][2] *= inv1;  acc[n8][3] *= inv1;
            }
        }

        // PV with register P fragments
        float acc2[4][4];
#pragma unroll
        for (int n8 = 0; n8 < 4; n8++)
#pragma unroll
            for (int r = 0; r < 4; r++) acc2[n8][r] = 0.f;

#pragma unroll
        for (int ks = 0; ks < 4; ks++) {
            uint32_t ph[4], pl[4];
            ph[0] = pack_hi2(acc[2 * ks][0],     acc[2 * ks][1]);
            ph[1] = pack_hi2(acc[2 * ks][2],     acc[2 * ks][3]);
            ph[2] = pack_hi2(acc[2 * ks + 1][0], acc[2 * ks + 1][1]);
            ph[3] = pack_hi2(acc[2 * ks + 1][2], acc[2 * ks + 1][3]);
            pl[0] = pack_lo2(acc[2 * ks][0],     acc[2 * ks][1]);
            pl[1] = pack_lo2(acc[2 * ks][2],     acc[2 * ks][3]);
            pl[2] = pack_lo2(acc[2 * ks + 1][0], acc[2 * ks + 1][1]);
            pl[3] = pack_lo2(acc[2 * ks + 1][2], acc[2 * ks + 1][3]);

            const int bcol = ks * 16 + ((quad & 1) << 3);
#pragma unroll
            for (int np = 0; np < 2; np++) {
                int brow = np * 16 + ((quad >> 1) << 3) + l8;
                uint32_t bo = (uint32_t)(brow * LV + bcol) * 2;
                uint32_t bq[4];
                ldm4(bq, uVH + bo);
                mma_bf16(acc2[2 * np + 0], ph, bq + 0);
                mma_bf16(acc2[2 * np + 1], ph, bq + 2);
                mma_bf16(acc2[2 * np + 0], pl, bq + 0);
                mma_bf16(acc2[2 * np + 1], pl, bq + 2);
                ldm4(bq, uVL + bo);
                mma_bf16(acc2[2 * np + 0], ph, bq + 0);
                mma_bf16(acc2[2 * np + 1], ph, bq + 2);
            }
        }

#pragma unroll
        for (int kf = 0; kf < 2; kf++) {
            cxh[it][kf * 4 + 0] = pack_hi2(acc2[2 * kf][0],     acc2[2 * kf][1]);
            cxh[it][kf * 4 + 1] = pack_hi2(acc2[2 * kf][2],     acc2[2 * kf][3]);
            cxh[it][kf * 4 + 2] = pack_hi2(acc2[2 * kf + 1][0], acc2[2 * kf + 1][1]);
            cxh[it][kf * 4 + 3] = pack_hi2(acc2[2 * kf + 1][2], acc2[2 * kf + 1][3]);
            cxl[it][kf * 4 + 0] = pack_lo2(acc2[2 * kf][0],     acc2[2 * kf][1]);
            cxl[it][kf * 4 + 1] = pack_lo2(acc2[2 * kf][2],     acc2[2 * kf][3]);
            cxl[it][kf * 4 + 2] = pack_lo2(acc2[2 * kf + 1][0], acc2[2 * kf + 1][1]);
            cxl[it][kf * 4 + 3] = pack_lo2(acc2[2 * kf + 1][2], acc2[2 * kf + 1][3]);
        }
        asm volatile("bar.sync %0, 128;" :: "r"(g + 1) : "memory");
    }

    __syncthreads();   // attn scratch dead; switch to proj layout

    // =================== proj: 8 passes of n32, double-buffered staging =========
    float* RED = (float*)(smraw + 4 * WBBUF);

    auto stageWB = [&](int p, int buf) {
        const uint32_t WBH = sb + (uint32_t)(g * 2 + buf) * WBBUF;
        const uint32_t WBL = WBH + 8704;
#pragma unroll
        for (int rep = 0; rep < 4; rep++) {
            int idx = rep * 128 + tg;
            int row = idx >> 4, cg = idx & 15;
            uint32_t so = (uint32_t)(row * LWB + cg * 8) * 2;
            size_t go = (size_t)(p * 32 + row) * 256 + g * 128 + cg * 8;
            cpasync16(WBH + so, g_wproj_hi + go);
            cpasync16(WBL + so, g_wproj_lo + go);
        }
        asm volatile("cp.async.commit_group;" ::: "memory");
    };

    stageWB(0, 0);

    for (int p = 0; p < 8; p++) {
        if (p + 1 < 8) {
            stageWB(p + 1, (p + 1) & 1);
            asm volatile("cp.async.wait_group 1;" ::: "memory");
        } else {
            asm volatile("cp.async.wait_group 0;" ::: "memory");
        }
        asm volatile("bar.sync %0, 128;" :: "r"(g + 1) : "memory");

        const uint32_t uWBH = sb + (uint32_t)(g * 2 + (p & 1)) * WBBUF;
        const uint32_t uWBL = uWBH + 8704;

        float pacc[4][4];
#pragma unroll
        for (int n8 = 0; n8 < 4; n8++)
#pragma unroll
            for (int r = 0; r < 4; r++) pacc[n8][r] = 0.f;

#pragma unroll
        for (int it = 0; it < 4; it++) {
#pragma unroll
            for (int kf = 0; kf < 2; kf++) {
                const int bcol = it * 32 + kf * 16 + ((quad & 1) << 3);
#pragma unroll
                for (int np = 0; np < 2; np++) {
                    int brow = np * 16 + ((quad >> 1) << 3) + l8;
                    uint32_t bo = (uint32_t)(brow * LWB + bcol) * 2;
                    uint32_t bq[4];
                    ldm4(bq, uWBH + bo);
                    mma_bf16(pacc[2 * np + 0], &cxh[it][kf * 4], bq + 0);
                    mma_bf16(pacc[2 * np + 1], &cxh[it][kf * 4], bq + 2);
                    mma_bf16(pacc[2 * np + 0], &cxl[it][kf * 4], bq + 0);
                    mma_bf16(pacc[2 * np + 1], &cxl[it][kf * 4], bq + 2);
                    ldm4(bq, uWBL + bo);
                    mma_bf16(pacc[2 * np + 0], &cxh[it][kf * 4], bq + 0);
                    mma_bf16(pacc[2 * np + 1], &cxh[it][kf * 4], bq + 2);
                }
            }
        }

        // cross-group reduction: g1 writes partials, g0 adds + stores
        const int r0 = wm * 16 + (lane >> 2);
        const int c2 = (lane & 3) * 2;
        if (g == 1) {
#pragma unroll
            for (int n8 = 0; n8 < 4; n8++) {
                *(float2*)&RED[r0 * LRED + n8 * 8 + c2]       = make_float2(pacc[n8][0], pacc[n8][1]);
                *(float2*)&RED[(r0 + 8) * LRED + n8 * 8 + c2] = make_float2(pacc[n8][2], pacc[n8][3]);
            }
        }
        __syncthreads();
        if (g == 0) {
#pragma unroll
            for (int n8 = 0; n8 < 4; n8++) {
                int gc = p * 32 + n8 * 8 + c2;
                float b0 = proj_b[gc], b1 = proj_b[gc + 1];
                float2 q0 = *(const float2*)&RED[r0 * LRED + n8 * 8 + c2];
                float2 q1 = *(const float2*)&RED[(r0 + 8) * LRED + n8 * 8 + c2];
                float2 v0 = make_float2(pacc[n8][0] + q0.x + b0, pacc[n8][1] + q0.y + b1);
                float2 v1 = make_float2(pacc[n8][2] + q1.x + b0, pacc[n8][3] + q1.y + b1);
                *(float2*)&out[((size_t)win * 64 + r0) * 256 + gc]     = v0;
                *(float2*)&out[((size_t)win * 64 + r0 + 8) * 256 + gc] = v1;
            }
        }
        __syncthreads();   // RED free before next pass writes
    }
}

// ===========================================================================
extern "C" void kernel_launch(void* const* d_in, const int* in_sizes, int n_in,
                              void* d_out, int out_size)
{
    const float* x            = (const float*)d_in[0];
    const float* mask         = (const float*)d_in[1];
    const float* qkv_w        = (const float*)d_in[2];
    const float* q_bias       = (const float*)d_in[3];
    const float* v_bias       = (const float*)d_in[4];
    const float* logit_scale  = (const float*)d_in[5];
    const float* coords_table = (const float*)d_in[6];
    const float* mlp1_w       = (const float*)d_in[7];
    const float* mlp1_b       = (const float*)d_in[8];
    const float* mlp2_w       = (const float*)d_in[9];
    const float* proj_w       = (const float*)d_in[10];
    const float* proj_b       = (const float*)d_in[11];
    const int*   rel_pos_idx  = (const int*)d_in[12];
    float* out = (float*)d_out;

    cudaFuncSetAttribute(gemm_qkv_kernel,
                         cudaFuncAttributeMaxDynamicSharedMemorySize, SMEM_G);

    prep_x_kernel<<<4096, 256>>>(x);
    prep_w_kernel<<<256, 256>>>(qkv_w, proj_w, q_bias, v_bias);
    cpb_kernel<<<1, 256>>>(coords_table, mlp1_w, mlp1_b, mlp2_w, rel_pos_idx);
    gemm_qkv_kernel<<<dim3(6, 1024), 256, SMEM_G>>>();
    attnproj_kernel<<<2048, 256>>>(mask, logit_scale, proj_b, out);
}

// round 16
// speedup vs baseline: 1.6770x; 1.0203x over previous
#include <cuda_runtime.h>
#include <cuda_bf16.h>
#include <cstdint>
#include <math.h>

// ===========================================================================
// WindowAttentionV2: split-bf16 mma.sync; fused attention+proj (ctx in regs).
// R13 base + merged prep launch + symmetric proj reduction.
// B=2048 win, N=64 tok, C=256, H=8, D=32.
// ===========================================================================

// ---- device scratch --------------------------------------------------------
__device__ float g_qkv[3u * 2048 * 8 * 2048];          // [(sec*2048+win)*8+h][tok*32+d]
__device__ __nv_bfloat16 g_xhi[131072u * 256];
__device__ __nv_bfloat16 g_xlo[131072u * 256];
__device__ __nv_bfloat16 g_wqkv_hi[768 * 256];         // [n][k]
__device__ __nv_bfloat16 g_wqkv_lo[768 * 256];
__device__ __nv_bfloat16 g_wproj_hi[256 * 256];
__device__ __nv_bfloat16 g_wproj_lo[256 * 256];
__device__ float g_rel_bias[8 * 64 * 64];
__device__ float g_bias_qkv[768];

// ---- helpers ----------------------------------------------------------------
__device__ __forceinline__ uint32_t smem_u32(const void* p) {
    uint32_t a;
    asm("{ .reg .u64 t; cvta.to.shared.u64 t, %1; cvt.u32.u64 %0, t; }"
        : "=r"(a) : "l"(p));
    return a;
}
__device__ __forceinline__ void mma_bf16(float* c, const uint32_t* a, const uint32_t* b) {
    asm volatile(
        "mma.sync.aligned.m16n8k16.row.col.f32.bf16.bf16.f32 "
        "{%0,%1,%2,%3}, {%4,%5,%6,%7}, {%8,%9}, {%0,%1,%2,%3};"
        : "+f"(c[0]), "+f"(c[1]), "+f"(c[2]), "+f"(c[3])
        : "r"(a[0]), "r"(a[1]), "r"(a[2]), "r"(a[3]), "r"(b[0]), "r"(b[1]));
}
__device__ __forceinline__ void ldm4(uint32_t* r, uint32_t addr) {
    asm volatile("ldmatrix.sync.aligned.m8n8.x4.shared.b16 {%0,%1,%2,%3}, [%4];"
                 : "=r"(r[0]), "=r"(r[1]), "=r"(r[2]), "=r"(r[3]) : "r"(addr));
}
__device__ __forceinline__ void cpasync16(uint32_t dst, const void* src) {
    asm volatile("cp.async.cg.shared.global [%0], [%1], 16;" :: "r"(dst), "l"(src));
}
__device__ __forceinline__ void bf_split(float v, __nv_bfloat16& hi, __nv_bfloat16& lo) {
    hi = __float2bfloat16(v);
    lo = __float2bfloat16(v - __bfloat162float(hi));
}
__device__ __forceinline__ uint32_t pack_bf(__nv_bfloat16 a, __nv_bfloat16 b) {
    return (uint32_t)__bfloat16_as_ushort(a) | ((uint32_t)__bfloat16_as_ushort(b) << 16);
}
__device__ __forceinline__ uint32_t pack_hi2(float a, float b) {
    return pack_bf(__float2bfloat16(a), __float2bfloat16(b));
}
__device__ __forceinline__ uint32_t pack_lo2(float a, float b) {
    __nv_bfloat16 ha = __float2bfloat16(a), hb = __float2bfloat16(b);
    return pack_bf(__float2bfloat16(a - __bfloat162float(ha)),
                   __float2bfloat16(b - __bfloat162float(hb)));
}

// ===========================================================================
// prep_all: block 0 -> cpb; blocks 1.. -> x fp32->bf16 hi/lo + weight prep.
// ===========================================================================
__global__ void prep_all_kernel(const float* __restrict__ x,
                                const float* __restrict__ qkv_w,
                                const float* __restrict__ proj_w,
                                const float* __restrict__ q_bias,
                                const float* __restrict__ v_bias,
                                const float* __restrict__ coords_table,
                                const float* __restrict__ mlp1_w,
                                const float* __restrict__ mlp1_b,
                                const float* __restrict__ mlp2_w,
                                const int*   __restrict__ rel_pos_index)
{
    __shared__ float bt[225 * 8];
    const int t = threadIdx.x;

    if (blockIdx.x == 0) {
        // ---- cpb: continuous position bias ---------------------------------
        if (t < 225) {
            float c0 = coords_table[t * 2 + 0];
            float c1 = coords_table[t * 2 + 1];
            float acc[8];
#pragma unroll
            for (int hh = 0; hh < 8; hh++) acc[hh] = 0.f;
            for (int k = 0; k < 512; k++) {
                float hv = fmaxf(c0 * mlp1_w[k] + c1 * mlp1_w[512 + k] + mlp1_b[k], 0.f);
#pragma unroll
                for (int hh = 0; hh < 8; hh++) acc[hh] += hv * mlp2_w[k * 8 + hh];
            }
#pragma unroll
            for (int hh = 0; hh < 8; hh++) bt[t * 8 + hh] = acc[hh];
        }
        __syncthreads();
        for (int idx = t; idx < 8 * 64 * 64; idx += blockDim.x) {
            int hh = idx >> 12;
            int ij = idx & 4095;
            float v = bt[rel_pos_index[ij] * 8 + hh];
            g_rel_bias[idx] = 16.f / (1.f + __expf(-v));
        }
        return;
    }

    const int gid = (blockIdx.x - 1) * blockDim.x + t;
    const int gsz = (gridDim.x - 1) * blockDim.x;

    // ---- x -> bf16 hi/lo ------------------------------------------------------
    for (int i = gid; i < 131072 * 64; i += gsz) {
        float4 f = ((const float4*)x)[i];
        __nv_bfloat16 h0, h1, h2, h3, l0, l1, l2, l3;
        bf_split(f.x, h0, l0); bf_split(f.y, h1, l1);
        bf_split(f.z, h2, l2); bf_split(f.w, h3, l3);
        ((__nv_bfloat162*)g_xhi)[2 * i]     = __nv_bfloat162(h0, h1);
        ((__nv_bfloat162*)g_xhi)[2 * i + 1] = __nv_bfloat162(h2, h3);
        ((__nv_bfloat162*)g_xlo)[2 * i]     = __nv_bfloat162(l0, l1);
        ((__nv_bfloat162*)g_xlo)[2 * i + 1] = __nv_bfloat162(l2, l3);
    }
    // ---- weights -> [n][k] bf16 hi/lo ------------------------------------------
    for (int i = gid; i < 768 * 256; i += gsz) {
        int n = i >> 8, k = i & 255;
        __nv_bfloat16 hi, lo;
        bf_split(qkv_w[(size_t)k * 768 + n], hi, lo);
        g_wqkv_hi[i] = hi; g_wqkv_lo[i] = lo;
    }
    for (int i = gid; i < 256 * 256; i += gsz) {
        int n = i >> 8, k = i & 255;
        __nv_bfloat16 hi, lo;
        bf_split(proj_w[(size_t)k * 256 + n], hi, lo);
        g_wproj_hi[i] = hi; g_wproj_lo[i] = lo;
    }
    for (int i = gid; i < 768; i += gsz)
        g_bias_qkv[i] = (i < 256) ? q_bias[i] : ((i < 512) ? 0.f : v_bias[i - 512]);
}

// ===========================================================================
// gemm_qkv: C[128,128] tile, split bf16, cp.async k32 double buffer.
// grid (6, 1024). (R13-proven 437us)
// ===========================================================================
#define LDC 40
#define CH_B  (128 * LDC * 2)         // 10240
#define BUF_B (4 * CH_B)              // AH AL BH BL = 40960
#define SMEM_G (2 * BUF_B)            // 81920

__global__ void __launch_bounds__(256, 2)
gemm_qkv_kernel()
{
    extern __shared__ __nv_bfloat16 smb[];
    const uint32_t sb = smem_u32(smb);

    const int t = threadIdx.x, lane = t & 31, w = t >> 5;
    const int wm = w & 3, wn = w >> 2;
    const int ntile = blockIdx.x, mtile = blockIdx.y;

    const size_t aoff = (size_t)mtile * 128 * 256;
    const size_t boff = (size_t)ntile * 128 * 256;

    auto stage = [&](int s, int buf) {
        const int k0 = s * 32;
        const uint32_t AH = sb + buf * BUF_B;
        const uint32_t AL = AH + CH_B;
        const uint32_t BH = AL + CH_B;
        const uint32_t BL = BH + CH_B;
#pragma unroll
        for (int rep = 0; rep < 2; rep++) {
            int idx = rep * 256 + t;
            int row = idx >> 2, cg = idx & 3;
            uint32_t so = (uint32_t)(row * LDC + cg * 8) * 2;
            size_t go = (size_t)row * 256 + k0 + cg * 8;
            cpasync16(AH + so, g_xhi + aoff + go);
            cpasync16(AL + so, g_xlo + aoff + go);
            cpasync16(BH + so, g_wqkv_hi + boff + go);
            cpasync16(BL + so, g_wqkv_lo + boff + go);
        }
        asm volatile("cp.async.commit_group;" ::: "memory");
    };

    float acc[2][8][4];
#pragma unroll
    for (int mi = 0; mi < 2; mi++)
#pragma unroll
        for (int n8 = 0; n8 < 8; n8++)
#pragma unroll
            for (int r = 0; r < 4; r++) acc[mi][n8][r] = 0.f;

    stage(0, 0);
    stage(1, 1);

    const int quad = lane >> 3, l8 = lane & 7;
    const int brow_base = wn * 64 + ((quad >> 1) << 3) + l8;

    for (int s = 0; s < 8; s++) {
        if (s < 7) asm volatile("cp.async.wait_group 1;" ::: "memory");
        else       asm volatile("cp.async.wait_group 0;" ::: "memory");
        __syncthreads();

        const uint32_t AH = sb + (s & 1) * BUF_B;
        const uint32_t AL = AH + CH_B;
        const uint32_t BH = AL + CH_B;
        const uint32_t BL = BH + CH_B;

#pragma unroll
        for (int ks = 0; ks < 2; ks++) {
            uint32_t ah[2][4], al[2][4];
            {
                int arow = wm * 32 + (lane & 15);
                int acol = ks * 16 + ((lane >> 4) << 3);
                uint32_t ao = (uint32_t)(arow * LDC + acol) * 2;
                ldm4(ah[0], AH + ao);
                ldm4(ah[1], AH + ao + 16 * LDC * 2);
                ldm4(al[0], AL + ao);
                ldm4(al[1], AL + ao + 16 * LDC * 2);
            }
            const int bcol = ks * 16 + ((quad & 1) << 3);

            uint32_t bh[2][4], bl[2][4];
            {
                uint32_t bo = (uint32_t)(brow_base * LDC + bcol) * 2;
                ldm4(bh[0], BH + bo);
                ldm4(bl[0], BL + bo);
            }
#pragma unroll
            for (int np = 0; np < 4; np++) {
                const int cur = np & 1, nxt = cur ^ 1;
                if (np < 3) {
                    uint32_t bo = (uint32_t)((brow_base + (np + 1) * 16) * LDC + bcol) * 2;
                    ldm4(bh[nxt], BH + bo);
                    ldm4(bl[nxt], BL + bo);
                }
#pragma unroll
                for (int mi = 0; mi < 2; mi++) {
                    mma_bf16(acc[mi][2 * np + 0], ah[mi], bh[cur] + 0);
                    mma_bf16(acc[mi][2 * np + 1], ah[mi], bh[cur] + 2);
                    mma_bf16(acc[mi][2 * np + 0], al[mi], bh[cur] + 0);
                    mma_bf16(acc[mi][2 * np + 1], al[mi], bh[cur] + 2);
                    mma_bf16(acc[mi][2 * np + 0], ah[mi], bl[cur] + 0);
                    mma_bf16(acc[mi][2 * np + 1], ah[mi], bl[cur] + 2);
                }
            }
        }
        __syncthreads();
        if (s + 2 < 8) stage(s + 2, s & 1);
    }

    const int row_l = wm * 32 + (lane >> 2);
    const int col_l = wn * 64 + (lane & 3) * 2;
#pragma unroll
    for (int mi = 0; mi < 2; mi++) {
#pragma unroll
        for (int n8 = 0; n8 < 8; n8++) {
            int gc = ntile * 128 + col_l + n8 * 8;
            int sec = gc >> 8, hh = (gc >> 5) & 7, d = gc & 31;
            float b0 = g_bias_qkv[gc], b1 = g_bias_qkv[gc + 1];
#pragma unroll
            for (int half = 0; half < 2; half++) {
                int row = mtile * 128 + row_l + mi * 16 + half * 8;
                int win = row >> 6, tok = row & 63;
                size_t addr = (((size_t)sec * 2048 + win) * 8 + hh) * 2048
                              + (size_t)tok * 32 + d;
                float2 v;
                v.x = acc[mi][n8][2 * half + 0] + b0;
                v.y = acc[mi][n8][2 * half + 1] + b1;
                *(float2*)&g_qkv[addr] = v;
            }
        }
    }
}

// ===========================================================================
// attnproj: fused attention + proj. CTA = window, 256 thr = 2 groups x 4 warps.
// R13 base; proj reduction made symmetric (each warp does exactly one of
// write-partial / read+store per pass).
// ===========================================================================
#define LQ 40    // q/k hi/lo row stride (bf16)
#define LV 72    // VT row stride (bf16)
#define LWB 136  // proj B stage row stride (bf16)
#define LRED 36

#define GRP_BYTES 29696

__global__ void __launch_bounds__(256, 2)
attnproj_kernel(const float* __restrict__ mask,
                const float* __restrict__ logit_scale,
                const float* __restrict__ proj_b,
                float*       __restrict__ out)
{
    __shared__ __align__(16) char smraw[2 * GRP_BYTES];
    const uint32_t sb = smem_u32(smraw);

    const int t = threadIdx.x, lane = t & 31, w = t >> 5;
    const int g = w >> 2, wm = w & 3, tg = t & 127;
    const int win = blockIdx.x;
    const int quad = lane >> 3, l8 = lane & 7;

    const uint32_t gb = sb + g * GRP_BYTES;
    const uint32_t uQH = gb, uQL = gb + 5120, uKH = gb + 10240, uKL = gb + 15360;
    const uint32_t uVH = gb + 20480, uVL = gb + 25088;
    __nv_bfloat16* VTH = (__nv_bfloat16*)(smraw + g * GRP_BYTES + 20480);
    __nv_bfloat16* VTL = (__nv_bfloat16*)(smraw + g * GRP_BYTES + 25088);

    uint32_t cxh[4][8], cxl[4][8];

    // =================== attention: 4 heads per group =========================
    for (int it = 0; it < 4; it++) {
        const int h = g * 4 + it;
        const float* qg = g_qkv + (((size_t)0 * 2048 + win) * 8 + h) * 2048;
        const float* kg = g_qkv + (((size_t)1 * 2048 + win) * 8 + h) * 2048;
        const float* vg = g_qkv + (((size_t)2 * 2048 + win) * 8 + h) * 2048;

#pragma unroll
        for (int rep = 0; rep < 4; rep++) {
            int idx = rep * 128 + tg;
            int tok = idx >> 3, d4 = (idx & 7) * 4;
            float4 fv = *(const float4*)(vg + idx * 4);
            float vv[4] = {fv.x, fv.y, fv.z, fv.w};
#pragma unroll
            for (int j = 0; j < 4; j++) {
                __nv_bfloat16 hi, lo;
                bf_split(vv[j], hi, lo);
                VTH[(d4 + j) * LV + tok] = hi;
                VTL[(d4 + j) * LV + tok] = lo;
            }
        }

        {
            int r = tg & 63;
            const float* src = (tg < 64) ? (qg + r * 32) : (kg + r * 32);
            float4 rv[8];
            float s = 0.f;
#pragma unroll
            for (int i = 0; i < 8; i++) {
                rv[i] = *(const float4*)(src + i * 4);
                s += rv[i].x * rv[i].x + rv[i].y * rv[i].y
                   + rv[i].z * rv[i].z + rv[i].w * rv[i].w;
            }
            float inv = rsqrtf(fmaxf(s, 1e-24f));
            if (tg < 64) inv *= __expf(fminf(logit_scale[h], 4.605170185988092f));
            uint32_t dh = ((tg < 64) ? uQH : uKH) + (uint32_t)(r * LQ) * 2;
            uint32_t dl = ((tg < 64) ? uQL : uKL) + (uint32_t)(r * LQ) * 2;
#pragma unroll
            for (int i = 0; i < 8; i++) {
                float v0 = rv[i].x * inv, v1 = rv[i].y * inv;
                float v2 = rv[i].z * inv, v3 = rv[i].w * inv;
                asm volatile("st.shared.v2.b32 [%0], {%1,%2};"
                             :: "r"(dh + i * 8), "r"(pack_hi2(v0, v1)), "r"(pack_hi2(v2, v3)));
                asm volatile("st.shared.v2.b32 [%0], {%1,%2};"
                             :: "r"(dl + i * 8), "r"(pack_lo2(v0, v1)), "r"(pack_lo2(v2, v3)));
            }
        }
        asm volatile("bar.sync %0, 128;" :: "r"(g + 1) : "memory");

        float acc[8][4];
#pragma unroll
        for (int n8 = 0; n8 < 8; n8++)
#pragma unroll
            for (int r = 0; r < 4; r++) acc[n8][r] = 0.f;

#pragma unroll
        for (int ks = 0; ks < 2; ks++) {
            uint32_t ah[4], al[4];
            {
                int arow = wm * 16 + (lane & 15);
                int acol = ks * 16 + ((lane >> 4) << 3);
                uint32_t ao = (uint32_t)(arow * LQ + acol) * 2;
                ldm4(ah, uQH + ao);
                ldm4(al, uQL + ao);
            }
            const int bcol = ks * 16 + ((quad & 1) << 3);
#pragma unroll
            for (int np = 0; np < 4; np++) {
                int brow = np * 16 + ((quad >> 1) << 3) + l8;
                uint32_t bo = (uint32_t)(brow * LQ + bcol) * 2;
                uint32_t bq[4];
                ldm4(bq, uKH + bo);
                mma_bf16(acc[2 * np + 0], ah, bq + 0);
                mma_bf16(acc[2 * np + 1], ah, bq + 2);
                mma_bf16(acc[2 * np + 0], al, bq + 0);
                mma_bf16(acc[2 * np + 1], al, bq + 2);
                ldm4(bq, uKL + bo);
                mma_bf16(acc[2 * np + 0], ah, bq + 0);
                mma_bf16(acc[2 * np + 1], ah, bq + 2);
            }
        }

        {
            const float* rb = g_rel_bias + h * 4096;
            const float* mk = mask + (size_t)(win & 255) * 4096;
            const int i0 = wm * 16 + (lane >> 2);
            const int i1 = i0 + 8;
            const int jc = (lane & 3) * 2;
#pragma unroll
            for (int n8 = 0; n8 < 8; n8++) {
                int o0 = i0 * 64 + n8 * 8 + jc;
                int o1 = i1 * 64 + n8 * 8 + jc;
                float2 r0 = *(const float2*)(rb + o0), m0 = *(const float2*)(mk + o0);
                float2 r1 = *(const float2*)(rb + o1), m1 = *(const float2*)(mk + o1);
                acc[n8][0] += r0.x + m0.x;  acc[n8][1] += r0.y + m0.y;
                acc[n8][2] += r1.x + m1.x;  acc[n8][3] += r1.y + m1.y;
            }
            float mx0 = -1e30f, mx1 = -1e30f;
#pragma unroll
            for (int n8 = 0; n8 < 8; n8++) {
                mx0 = fmaxf(mx0, fmaxf(acc[n8][0], acc[n8][1]));
                mx1 = fmaxf(mx1, fmaxf(acc[n8][2], acc[n8][3]));
            }
            mx0 = fmaxf(mx0, __shfl_xor_sync(0xffffffffu, mx0, 1));
            mx0 = fmaxf(mx0, __shfl_xor_sync(0xffffffffu, mx0, 2));
            mx1 = fmaxf(mx1, __shfl_xor_sync(0xffffffffu, mx1, 1));
            mx1 = fmaxf(mx1, __shfl_xor_sync(0xffffffffu, mx1, 2));
            float s0 = 0.f, s1 = 0.f;
#pragma unroll
            for (int n8 = 0; n8 < 8; n8++) {
                acc[n8][0] = __expf(acc[n8][0] - mx0);
                acc[n8][1] = __expf(acc[n8][1] - mx0);
                acc[n8][2] = __expf(acc[n8][2] - mx1);
                acc[n8][3] = __expf(acc[n8][3] - mx1);
                s0 += acc[n8][0] + acc[n8][1];
                s1 += acc[n8][2] + acc[n8][3];
            }
            s0 += __shfl_xor_sync(0xffffffffu, s0, 1);
            s0 += __shfl_xor_sync(0xffffffffu, s0, 2);
            s1 += __shfl_xor_sync(0xffffffffu, s1, 1);
            s1 += __shfl_xor_sync(0xffffffffu, s1, 2);
            float inv0 = 1.f / s0, inv1 = 1.f / s1;
#pragma unroll
            for (int n8 = 0; n8 < 8; n8++) {
                acc[n8][0] *= inv0;  acc[n8][1] *= inv0;
                acc[n8][2] *= inv1;  acc[n8][3] *= inv1;
            }
        }

        float acc2[4][4];
#pragma unroll
        for (int n8 = 0; n8 < 4; n8++)
#pragma unroll
            for (int r = 0; r < 4; r++) acc2[n8][r] = 0.f;

#pragma unroll
        for (int ks = 0; ks < 4; ks++) {
            uint32_t ph[4], pl[4];
            ph[0] = pack_hi2(acc[2 * ks][0],     acc[2 * ks][1]);
            ph[1] = pack_hi2(acc[2 * ks][2],     acc[2 * ks][3]);
            ph[2] = pack_hi2(acc[2 * ks + 1][0], acc[2 * ks + 1][1]);
            ph[3] = pack_hi2(acc[2 * ks + 1][2], acc[2 * ks + 1][3]);
            pl[0] = pack_lo2(acc[2 * ks][0],     acc[2 * ks][1]);
            pl[1] = pack_lo2(acc[2 * ks][2],     acc[2 * ks][3]);
            pl[2] = pack_lo2(acc[2 * ks + 1][0], acc[2 * ks + 1][1]);
            pl[3] = pack_lo2(acc[2 * ks + 1][2], acc[2 * ks + 1][3]);

            const int bcol = ks * 16 + ((quad & 1) << 3);
#pragma unroll
            for (int np = 0; np < 2; np++) {
                int brow = np * 16 + ((quad >> 1) << 3) + l8;
                uint32_t bo = (uint32_t)(brow * LV + bcol) * 2;
                uint32_t bq[4];
                ldm4(bq, uVH + bo);
                mma_bf16(acc2[2 * np + 0], ph, bq + 0);
                mma_bf16(acc2[2 * np + 1], ph, bq + 2);
                mma_bf16(acc2[2 * np + 0], pl, bq + 0);
                mma_bf16(acc2[2 * np + 1], pl, bq + 2);
                ldm4(bq, uVL + bo);
                mma_bf16(acc2[2 * np + 0], ph, bq + 0);
                mma_bf16(acc2[2 * np + 1], ph, bq + 2);
            }
        }

#pragma unroll
        for (int kf = 0; kf < 2; kf++) {
            cxh[it][kf * 4 + 0] = pack_hi2(acc2[2 * kf][0],     acc2[2 * kf][1]);
            cxh[it][kf * 4 + 1] = pack_hi2(acc2[2 * kf][2],     acc2[2 * kf][3]);
            cxh[it][kf * 4 + 2] = pack_hi2(acc2[2 * kf + 1][0], acc2[2 * kf + 1][1]);
            cxh[it][kf * 4 + 3] = pack_hi2(acc2[2 * kf + 1][2], acc2[2 * kf + 1][3]);
            cxl[it][kf * 4 + 0] = pack_lo2(acc2[2 * kf][0],     acc2[2 * kf][1]);
            cxl[it][kf * 4 + 1] = pack_lo2(acc2[2 * kf][2],     acc2[2 * kf][3]);
            cxl[it][kf * 4 + 2] = pack_lo2(acc2[2 * kf + 1][0], acc2[2 * kf + 1][1]);
            cxl[it][kf * 4 + 3] = pack_lo2(acc2[2 * kf + 1][2], acc2[2 * kf + 1][3]);
        }
        asm volatile("bar.sync %0, 128;" :: "r"(g + 1) : "memory");
    }

    __syncthreads();

    // =================== proj: 8 passes of n32, k-split by group ================
    const uint32_t uWBH = sb + g * 17408;
    const uint32_t uWBL = uWBH + 8704;
    float* REDA = (float*)(smraw + 2 * 17408);          // partials rows 32..63 (g0)
    float* REDB = REDA + 32 * LRED;                     // partials rows 0..31  (g1)

    for (int p = 0; p < 8; p++) {
#pragma unroll
        for (int rep = 0; rep < 4; rep++) {
            int idx = rep * 128 + tg;
            int row = idx >> 4, cg = idx & 15;
            uint32_t so = (uint32_t)(row * LWB + cg * 8) * 2;
            size_t go = (size_t)(p * 32 + row) * 256 + g * 128 + cg * 8;
            cpasync16(uWBH + so, g_wproj_hi + go);
            cpasync16(uWBL + so, g_wproj_lo + go);
        }
        asm volatile("cp.async.commit_group;" ::: "memory");
        asm volatile("cp.async.wait_group 0;" ::: "memory");
        asm volatile("bar.sync %0, 128;" :: "r"(g + 1) : "memory");

        float pacc[4][4];
#pragma unroll
        for (int n8 = 0; n8 < 4; n8++)
#pragma unroll
            for (int r = 0; r < 4; r++) pacc[n8][r] = 0.f;

#pragma unroll
        for (int it = 0; it < 4; it++) {
#pragma unroll
            for (int kf = 0; kf < 2; kf++) {
                const int bcol = it * 32 + kf * 16 + ((quad & 1) << 3);
#pragma unroll
                for (int np = 0; np < 2; np++) {
                    int brow = np * 16 + ((quad >> 1) << 3) + l8;
                    uint32_t bo = (uint32_t)(brow * LWB + bcol) * 2;
                    uint32_t bq[4];
                    ldm4(bq, uWBH + bo);
                    mma_bf16(pacc[2 * np + 0], &cxh[it][kf * 4], bq + 0);
                    mma_bf16(pacc[2 * np + 1], &cxh[it][kf * 4], bq + 2);
                    mma_bf16(pacc[2 * np + 0], &cxl[it][kf * 4], bq + 0);
                    mma_bf16(pacc[2 * np + 1], &cxl[it][kf * 4], bq + 2);
                    ldm4(bq, uWBL + bo);
                    mma_bf16(pacc[2 * np + 0], &cxh[it][kf * 4], bq + 0);
                    mma_bf16(pacc[2 * np + 1], &cxh[it][kf * 4], bq + 2);
                }
            }
        }

        // ---- symmetric cross-group reduction ---------------------------------
        // g0: wm<2 finalize rows 0..31 (reads REDB), wm>=2 write REDA (rows 32..63)
        // g1: wm<2 write REDB (rows 0..31), wm>=2 finalize rows 32..63 (reads REDA)
        const int r0 = wm * 16 + (lane >> 2);
        const int c2 = (lane & 3) * 2;
        const bool writer = (g == 0) ? (wm >= 2) : (wm < 2);
        if (writer) {
            float* R = (g == 0) ? REDA : REDB;
            int rr = (g == 0) ? (r0 - 32) : r0;
#pragma unroll
            for (int n8 = 0; n8 < 4; n8++) {
                *(float2*)&R[rr * LRED + n8 * 8 + c2]       = make_float2(pacc[n8][0], pacc[n8][1]);
                *(float2*)&R[(rr + 8) * LRED + n8 * 8 + c2] = make_float2(pacc[n8][2], pacc[n8][3]);
            }
        }
        __syncthreads();
        if (!writer) {
            float* R = (g == 0) ? REDB : REDA;
            int rr = (g == 0) ? r0 : (r0 - 32);
#pragma unroll
            for (int n8 = 0; n8 < 4; n8++) {
                int gc = p * 32 + n8 * 8 + c2;
                float b0 = proj_b[gc], b1 = proj_b[gc + 1];
                float2 q0 = *(const float2*)&R[rr * LRED + n8 * 8 + c2];
                float2 q1 = *(const float2*)&R[(rr + 8) * LRED + n8 * 8 + c2];
                float2 v0 = make_float2(pacc[n8][0] + q0.x + b0, pacc[n8][1] + q0.y + b1);
                float2 v1 = make_float2(pacc[n8][2] + q1.x + b0, pacc[n8][3] + q1.y + b1);
                *(float2*)&out[((size_t)win * 64 + r0) * 256 + gc]     = v0;
                *(float2*)&out[((size_t)win * 64 + r0 + 8) * 256 + gc] = v1;
            }
        }
        __syncthreads();
    }
}

// ===========================================================================
extern "C" void kernel_launch(void* const* d_in, const int* in_sizes, int n_in,
                              void* d_out, int out_size)
{
    const float* x            = (const float*)d_in[0];
    const float* mask         = (const float*)d_in[1];
    const float* qkv_w        = (const float*)d_in[2];
    const float* q_bias       = (const float*)d_in[3];
    const float* v_bias       = (const float*)d_in[4];
    const float* logit_scale  = (const float*)d_in[5];
    const float* coords_table = (const float*)d_in[6];
    const float* mlp1_w       = (const float*)d_in[7];
    const float* mlp1_b       = (const float*)d_in[8];
    const float* mlp2_w       = (const float*)d_in[9];
    const float* proj_w       = (const float*)d_in[10];
    const float* proj_b       = (const float*)d_in[11];
    const int*   rel_pos_idx  = (const int*)d_in[12];
    float* out = (float*)d_out;

    cudaFuncSetAttribute(gemm_qkv_kernel,
                         cudaFuncAttributeMaxDynamicSharedMemorySize, SMEM_G);

    prep_all_kernel<<<4097, 256>>>(x, qkv_w, proj_w, q_bias, v_bias,
                                   coords_table, mlp1_w, mlp1_b, mlp2_w,
                                   rel_pos_idx);
    gemm_qkv_kernel<<<dim3(6, 1024), 256, SMEM_G>>>();
    attnproj_kernel<<<2048, 256>>>(mask, logit_scale, proj_b, out);
}